// round 12
// baseline (speedup 1.0000x reference)
#include <cuda_runtime.h>
#include <cstdint>
#include <math.h>

#define BATCH 64
#define SEQ   2048
#define INP   256
#define HID   512
#define NCTA  128
#define BGR   8      // batches per CTA
#define JGR   32     // hidden columns per CTA

// ---------------- scratch (no allocations allowed) ----------------
__device__ float    g_hbuf[2 * BATCH * HID];   // double-buffered hidden state
__device__ float    g_opart[NCTA * 16];        // per-CTA readout partials
__device__ unsigned g_flags[NCTA];             // per-CTA epoch flags (monotone across replays)

// ---------------- packed fp32x2 FMA helpers (FFMA2) ----------------
__device__ __forceinline__ void fma2(unsigned long long &d, unsigned long long a, unsigned long long b) {
    asm("fma.rn.f32x2 %0, %1, %2, %0;" : "+l"(d) : "l"(a), "l"(b));
}
__device__ __forceinline__ unsigned long long pack2(float lo, float hi) {
    unsigned long long r;
    asm("mov.b64 %0, {%1, %2};" : "=l"(r) : "f"(lo), "f"(hi));
    return r;
}
__device__ __forceinline__ float lo2(unsigned long long v) { return __uint_as_float((unsigned)v); }
__device__ __forceinline__ float hi2(unsigned long long v) { return __uint_as_float((unsigned)(v >> 32)); }

// ---------------- sync ops (no scope>=cluster FENCES in step path) ----------------
__device__ __forceinline__ unsigned ldacq(const unsigned* p) {
    unsigned v;
    asm volatile("ld.acquire.gpu.global.u32 %0, [%1];" : "=r"(v) : "l"(p) : "memory");
    return v;
}
__device__ __forceinline__ void strel(unsigned* p, unsigned v) {
    asm volatile("st.release.gpu.global.u32 [%0], %1;" :: "l"(p), "r"(v) : "memory");
}

// ---------------- cp.async helpers ----------------
__device__ __forceinline__ uint32_t smem_u32(const void* p) {
    uint32_t a;
    asm("{ .reg .u64 t; cvta.to.shared.u64 t, %1; cvt.u32.u64 %0, t; }" : "=r"(a) : "l"(p));
    return a;
}
__device__ __forceinline__ void cpasync16(uint32_t dst, const void* src) {
    asm volatile("cp.async.cg.shared.global [%0], [%1], 16;" :: "r"(dst), "l"(src));
}
#define CP_COMMIT() asm volatile("cp.async.commit_group;" ::: "memory")
#define CP_WAIT1()  asm volatile("cp.async.wait_group 1;" ::: "memory")
#define CP_WAIT0()  asm volatile("cp.async.wait_group 0;" ::: "memory")

// 5-stage butterfly: array a[32]; afterwards lane L holds sum-over-lanes of a[L].
#define BFLY_ALL(a, lane)                                                   \
    do {                                                                    \
        _Pragma("unroll")                                                   \
        for (int off = 16, nk = 16; off >= 1; off >>= 1, nk >>= 1) {        \
            const bool up = ((lane) & off) != 0;                            \
            _Pragma("unroll")                                               \
            for (int i = 0; i < nk; i++) {                                  \
                float send = up ? (a)[i] : (a)[i + nk];                     \
                float recv = __shfl_xor_sync(0xffffffffu, send, off);       \
                (a)[i] = (up ? (a)[i + nk] : (a)[i]) + recv;                \
            }                                                               \
        }                                                                   \
    } while (0)

// dynamic smem layout (floats)
#define SM_XSH 0                         // Xsh[2][8][256]   16 KB
#define SM_WSH (SM_XSH + 2 * 8 * 256)    // Wsh[32][256]     32 KB
#define SM_HSH (SM_WSH + 32 * 256)       // hsh[8][512]      16 KB
#define SM_TOT ((SM_HSH + 8 * 512) * 4)  // 64 KB

// =====================================================================
// ONE persistent kernel: wx (pipelined 1 step ahead, via cp.async X
// prefetch 2 steps ahead), tanh-RNN scan, and fused readout.
// 128 CTAs: cta = bg*16+jg -> 8 batches x 32 hidden cols. Group-local
// flag sync (single-warp acquire poll), U slice in registers, FFMA2
// everywhere, butterfly reductions leave output L in lane L.
// =====================================================================
__global__ __launch_bounds__(256, 1)
void fused_kernel(const float* __restrict__ x,  const float* __restrict__ Ww,
                  const float* __restrict__ Wb, const float* __restrict__ Uw,
                  const float* __restrict__ Ub, const float* __restrict__ Vw,
                  const float* __restrict__ Vb, float* __restrict__ out) {
    extern __shared__ float sm[];
    float* Xsh = sm + SM_XSH;
    float* Wsh = sm + SM_WSH;
    float* hsh = sm + SM_HSH;

    const int t    = threadIdx.x;
    const int cta  = blockIdx.x;
    const int bg   = cta >> 4;
    const int jg   = cta & 15;
    const int b0   = bg * BGR;
    const int j0   = jg * JGR;
    const int w    = t >> 5;
    const int lane = t & 31;

    // after butterfly: lane L holds output o=L -> b = L>>2, jl = L&3
    const int ob = lane >> 2;
    const int oj = (w << 2) | (lane & 3);

    unsigned* const fgrp = g_flags + bg * 16;
    const unsigned base = g_flags[cta];          // replay-safe epoch base

    // ---- one-time: U slice into registers ----
    ulonglong2 ureg[4][4];
#pragma unroll
    for (int qi = 0; qi < 4; qi++) {
        const int kb = qi * 128 + lane * 4;
#pragma unroll
        for (int j = 0; j < 4; j++) {
            const float* up = Uw + (size_t)kb * HID + (j0 + w * 4 + j);
            ureg[qi][j].x = pack2(up[0], up[HID]);
            ureg[qi][j].y = pack2(up[2 * HID], up[3 * HID]);
        }
    }
    const float ubj = Ub[j0 + oj];
    const float wbj = Wb[j0 + oj];

    // ---- one-time: W slice transposed into smem: Wsh[jj][k] = W[k][j0+jj] ----
    for (int i = t; i < JGR * INP; i += 256) {
        int jj = i & 31;
        int k  = i >> 5;
        Wsh[jj * INP + k] = Ww[(size_t)k * HID + j0 + jj];
    }

    // ---- X staging: thread t copies chunks t and t+256 of 512 x 16B ----
    // chunk c: row r = c>>6, f4 col = c&63
    const int xc0_r = t >> 6,          xc0_c = t & 63;
    const int xc1_r = (t + 256) >> 6,  xc1_c = (t + 256) & 63;
    const uint32_t xsh_base = smem_u32(Xsh);
#define STAGE_X(sp)                                                                     \
    do {                                                                                \
        const uint32_t dbuf = ((sp) & 1) * 2048u * 4u;                                  \
        cpasync16(xsh_base + dbuf + (uint32_t)(xc0_r * 256 + xc0_c * 4) * 4u,           \
                  x + ((size_t)(b0 + xc0_r) * SEQ + (sp)) * INP + xc0_c * 4);           \
        cpasync16(xsh_base + dbuf + (uint32_t)(xc1_r * 256 + xc1_c * 4) * 4u,           \
                  x + ((size_t)(b0 + xc1_r) * SEQ + (sp)) * INP + xc1_c * 4);           \
    } while (0)

    // wx compute for step sp (reads Xsh[sp&1] + Wsh): returns lane's wx value
#define WX_COMPUTE(sp, dst)                                                             \
    do {                                                                                \
        unsigned long long wacc[32];                                                    \
        _Pragma("unroll")                                                               \
        for (int o = 0; o < 32; o++) wacc[o] = 0ull;                                    \
        const float* xb = Xsh + ((sp) & 1) * 2048;                                      \
        _Pragma("unroll")                                                               \
        for (int qi = 0; qi < 2; qi++) {                                                \
            const int kb = qi * 128 + lane * 4;                                         \
            ulonglong2 xq[8], wq[4];                                                    \
            _Pragma("unroll")                                                           \
            for (int r = 0; r < 8; r++) xq[r] = *(const ulonglong2*)(xb + r * INP + kb);\
            _Pragma("unroll")                                                           \
            for (int j = 0; j < 4; j++) wq[j] = *(const ulonglong2*)(Wsh + (w * 4 + j) * INP + kb); \
            _Pragma("unroll")                                                           \
            for (int b = 0; b < 8; b++)                                                 \
                _Pragma("unroll")                                                       \
                for (int j = 0; j < 4; j++) {                                           \
                    fma2(wacc[b * 4 + j], xq[b].x, wq[j].x);                            \
                    fma2(wacc[b * 4 + j], xq[b].y, wq[j].y);                            \
                }                                                                       \
        }                                                                               \
        float vv[32];                                                                   \
        _Pragma("unroll")                                                               \
        for (int o = 0; o < 32; o++) vv[o] = lo2(wacc[o]) + hi2(wacc[o]);               \
        BFLY_ALL(vv, lane);                                                             \
        (dst) = vv[0] + wbj;                                                            \
    } while (0)

    // ---- prologue: stage X(0), X(1); compute wx(0) ----
    STAGE_X(0); CP_COMMIT();
    STAGE_X(1); CP_COMMIT();
    CP_WAIT0();
    __syncthreads();                 // X(0)/X(1) + Wsh visible to all
    float wx_cur;
    WX_COMPUTE(0, wx_cur);
    float h_last = 0.0f;

    for (int s = 0; s < SEQ; s++) {
        // 1. prefetch X(s+2) (always commit, even empty, for group bookkeeping)
        if (s + 2 < SEQ) STAGE_X(s + 2);
        CP_COMMIT();
        CP_WAIT1();                  // X(s+1) copies (this thread) done
        __syncthreads();             // X(s+1) visible to all threads

        // 2. compute wx(s+1) while flags settle
        float wx_next = 0.0f;
        if (s + 1 < SEQ) WX_COMPUTE(s + 1, wx_next);

        // 3. sync on h(s) availability + stage it
        if (s == 0) {
            for (int i = t; i < BGR * HID; i += 256) hsh[i] = 0.0f;
            __syncthreads();
        } else {
            if (w == 0) {            // single-warp acquire poll of 16 group flags
                const unsigned tgt = base + (unsigned)s;
                unsigned v = tgt;
                if (lane < 16) v = ldacq(fgrp + lane);
                while (__any_sync(0xffffffffu, (int)(v - tgt) < 0)) {
                    if (lane < 16 && (int)(v - tgt) < 0) v = ldacq(fgrp + lane);
                }
            }
            __syncthreads();         // releases warps 1..7; extends acquire to CTA
            const float* hsrc = g_hbuf + (s & 1) * (BATCH * HID) + (size_t)b0 * HID;
            for (int i = t; i < (BGR * HID) / 4; i += 256)
                ((float4*)hsh)[i] = ((const float4*)hsrc)[i];
            __syncthreads();
        }

        // 4. scan compute: 8b x 4j FFMA2 tile, U from registers
        unsigned long long acc[32];
#pragma unroll
        for (int o = 0; o < 32; o++) acc[o] = 0ull;
#pragma unroll
        for (int qi = 0; qi < 4; qi++) {
            const int kb = qi * 128 + lane * 4;
            ulonglong2 hq[8];
#pragma unroll
            for (int b = 0; b < 8; b++)
                hq[b] = *(const ulonglong2*)(hsh + b * HID + kb);
#pragma unroll
            for (int b = 0; b < 8; b++)
#pragma unroll
                for (int j = 0; j < 4; j++) {
                    fma2(acc[b * 4 + j], hq[b].x, ureg[qi][j].x);
                    fma2(acc[b * 4 + j], hq[b].y, ureg[qi][j].y);
                }
        }
        float v[32];
#pragma unroll
        for (int o = 0; o < 32; o++) v[o] = lo2(acc[o]) + hi2(acc[o]);
        BFLY_ALL(v, lane);

        float hnew = tanhf(wx_cur + ubj + v[0]);
        h_last = hnew;
        g_hbuf[((s + 1) & 1) * (BATCH * HID) + (size_t)(b0 + ob) * HID + (j0 + oj)] = hnew;

        // 5. order h stores before release; protect hsh/Xsh for next iter
        __syncthreads();
        if (t == 0) strel(g_flags + cta, base + (unsigned)s + 1u);

        wx_cur = wx_next;
    }

    // ---- fused readout ----
    // dump final h tile into hsh as [8][32]
    hsh[ob * 32 + oj] = h_last;
    __syncthreads();
    if (w == 0 && lane < 16) {
        const int b = lane >> 1, o = lane & 1;
        float p = 0.0f;
#pragma unroll
        for (int j = 0; j < 32; j++)
            p += hsh[b * 32 + j] * Vw[(size_t)(j0 + j) * 2 + o];
        g_opart[cta * 16 + lane] = p;
    }
    __syncthreads();
    if (t == 0) strel(g_flags + cta, base + (unsigned)SEQ + 1u);

    if (jg == 0) {
        if (w == 0) {
            const unsigned tgt = base + (unsigned)SEQ + 1u;
            unsigned v2 = tgt;
            if (lane < 16) v2 = ldacq(fgrp + lane);
            while (__any_sync(0xffffffffu, (int)(v2 - tgt) < 0)) {
                if (lane < 16 && (int)(v2 - tgt) < 0) v2 = ldacq(fgrp + lane);
            }
        }
        __syncthreads();
        if (w == 0 && lane < 16) {
            const int b = lane >> 1, o = lane & 1;
            float ssum = Vb[o];
#pragma unroll
            for (int g = 0; g < 16; g++)
                ssum += g_opart[(bg * 16 + g) * 16 + lane];
            out[(size_t)(b0 + b) * 2 + o] = 1.0f / (1.0f + expf(-ssum));
        }
    }
}

// =====================================================================
extern "C" void kernel_launch(void* const* d_in, const int* in_sizes, int n_in,
                              void* d_out, int out_size) {
    const float* x  = (const float*)d_in[0];
    const float* Ww = (const float*)d_in[1];
    const float* Wb = (const float*)d_in[2];
    const float* Uw = (const float*)d_in[3];
    const float* Ub = (const float*)d_in[4];
    const float* Vw = (const float*)d_in[5];
    const float* Vb = (const float*)d_in[6];
    float* out = (float*)d_out;

    cudaFuncSetAttribute(fused_kernel, cudaFuncAttributeMaxDynamicSharedMemorySize, SM_TOT);
    fused_kernel<<<NCTA, 256, SM_TOT>>>(x, Ww, Wb, Uw, Ub, Vw, Vb, out);
}

// round 13
// speedup vs baseline: 1.0063x; 1.0063x over previous
#include <cuda_runtime.h>
#include <cstdint>
#include <math.h>

#define BATCH 64
#define SEQ   2048
#define INP   256
#define HID   512
#define NCTA  128
#define THR   512
#define BGR   8      // batches per CTA
#define JGR   32     // hidden columns per CTA

// ---------------- scratch (no allocations allowed) ----------------
__device__ float    g_hbuf[2 * BATCH * HID];   // double-buffered hidden state
__device__ float    g_opart[NCTA * 16];        // per-CTA readout partials
__device__ unsigned g_flags[NCTA];             // per-CTA epoch flags (monotone across replays)

// ---------------- packed fp32x2 FMA helpers (FFMA2) ----------------
__device__ __forceinline__ void fma2(unsigned long long &d, unsigned long long a, unsigned long long b) {
    asm("fma.rn.f32x2 %0, %1, %2, %0;" : "+l"(d) : "l"(a), "l"(b));
}
__device__ __forceinline__ unsigned long long pack2(float lo, float hi) {
    unsigned long long r;
    asm("mov.b64 %0, {%1, %2};" : "=l"(r) : "f"(lo), "f"(hi));
    return r;
}
__device__ __forceinline__ float lo2(unsigned long long v) { return __uint_as_float((unsigned)v); }
__device__ __forceinline__ float hi2(unsigned long long v) { return __uint_as_float((unsigned)(v >> 32)); }

// ---------------- sync ops (no scope>=cluster FENCES in step path) ----------------
__device__ __forceinline__ unsigned ldacq(const unsigned* p) {
    unsigned v;
    asm volatile("ld.acquire.gpu.global.u32 %0, [%1];" : "=r"(v) : "l"(p) : "memory");
    return v;
}
__device__ __forceinline__ void strel(unsigned* p, unsigned v) {
    asm volatile("st.release.gpu.global.u32 [%0], %1;" :: "l"(p), "r"(v) : "memory");
}

// ---------------- cp.async helpers ----------------
__device__ __forceinline__ uint32_t smem_u32(const void* p) {
    uint32_t a;
    asm("{ .reg .u64 t; cvta.to.shared.u64 t, %1; cvt.u32.u64 %0, t; }" : "=r"(a) : "l"(p));
    return a;
}
__device__ __forceinline__ void cpasync16(uint32_t dst, const void* src) {
    asm volatile("cp.async.cg.shared.global [%0], [%1], 16;" :: "r"(dst), "l"(src));
}
#define CP_COMMIT() asm volatile("cp.async.commit_group;" ::: "memory")
#define CP_WAIT1()  asm volatile("cp.async.wait_group 1;" ::: "memory")

// 4-stage butterfly over a[16] + final xor-1 fold (R9-verified mapping):
// afterwards EVEN lane L holds output o=(L>>1)&15.
#define BFLY16(a, lane)                                                     \
    do {                                                                    \
        _Pragma("unroll")                                                   \
        for (int off = 16, nk = 8; off >= 2; off >>= 1, nk >>= 1) {         \
            const bool up = ((lane) & off) != 0;                            \
            _Pragma("unroll")                                               \
            for (int i = 0; i < nk; i++) {                                  \
                float send = up ? (a)[i] : (a)[i + nk];                     \
                float recv = __shfl_xor_sync(0xffffffffu, send, off);       \
                (a)[i] = (up ? (a)[i + nk] : (a)[i]) + recv;                \
            }                                                               \
        }                                                                   \
        (a)[0] += __shfl_xor_sync(0xffffffffu, (a)[0], 1);                  \
    } while (0)

// =====================================================================
// ONE persistent kernel, 128 CTAs x 512 threads (16 warps = 4/SMSP).
// cta = bg*16+jg -> 8 batches x 32 hidden cols. Warp w: batches
// (w>>3)*4..+3, j cols (w&7)*4..+3 (4b x 4j tile, K over 32 lanes in
// quads). U (4 quads) and W (2 quads) slices live in registers. wx is
// pipelined one step ahead (cp.async X prefetch two ahead) and computed
// in the shadow of the h-stage LDG latency. Group-local flag sync with
// single-warp acquire poll; 3 barriers per step; fused readout.
// =====================================================================
__global__ __launch_bounds__(THR, 1)
void fused_kernel(const float* __restrict__ x,  const float* __restrict__ Ww,
                  const float* __restrict__ Wb, const float* __restrict__ Uw,
                  const float* __restrict__ Ub, const float* __restrict__ Vw,
                  const float* __restrict__ Vb, float* __restrict__ out) {
    __shared__ float Xsh[2][BGR * INP];   // 16 KB, double-buffered X tiles
    __shared__ float hsh[BGR * HID];      // 16 KB

    const int t    = threadIdx.x;
    const int cta  = blockIdx.x;
    const int bg   = cta >> 4;
    const int jg   = cta & 15;
    const int b0   = bg * BGR;
    const int j0   = jg * JGR;
    const int w    = t >> 5;
    const int lane = t & 31;
    const int wb   = w >> 3;      // batch half (0/1) -> batches wb*4..+3
    const int wj   = w & 7;       // j group -> cols wj*4..+3

    // writer mapping (R9-verified): even lane L -> o=(L>>1): b=(L>>3)&3, jl=(L>>1)&3
    const int ob  = (lane >> 3) & 3;
    const int ojl = (lane >> 1) & 3;
    const bool writer = ((lane & 1) == 0);
    const int babs  = b0 + wb * 4 + ob;            // absolute batch (writers)
    const int jabs  = j0 + wj * 4 + ojl;           // absolute hidden col (writers)

    unsigned* const fgrp = g_flags + bg * 16;
    const unsigned base = g_flags[cta];            // replay-safe epoch base

    // ---- one-time: U slice (4 quads) and W slice (2 quads) into registers ----
    ulonglong2 ureg[4][4], wreg[2][4];
#pragma unroll
    for (int qi = 0; qi < 4; qi++) {
        const int kb = qi * 128 + lane * 4;
#pragma unroll
        for (int j = 0; j < 4; j++) {
            const float* up = Uw + (size_t)kb * HID + (j0 + wj * 4 + j);
            ureg[qi][j].x = pack2(up[0], up[HID]);
            ureg[qi][j].y = pack2(up[2 * HID], up[3 * HID]);
        }
    }
#pragma unroll
    for (int qi = 0; qi < 2; qi++) {
        const int kb = qi * 128 + lane * 4;
#pragma unroll
        for (int j = 0; j < 4; j++) {
            const float* wp = Ww + (size_t)kb * HID + (j0 + wj * 4 + j);
            wreg[qi][j].x = pack2(wp[0], wp[HID]);
            wreg[qi][j].y = pack2(wp[2 * HID], wp[3 * HID]);
        }
    }
    const float ubj = Ub[jabs];
    const float wbj = Wb[jabs];

    // ---- X staging: thread t copies its single 16B chunk (512 x 16B = 8KB) ----
    const int xr = t >> 6;                 // batch row 0..7
    const int xc = t & 63;                 // float4 col 0..63
    const float* const xsrc = x + ((size_t)(b0 + xr) * SEQ) * INP + xc * 4;
    const uint32_t xdst0 = smem_u32(&Xsh[0][xr * INP + xc * 4]);
    const uint32_t xdst1 = smem_u32(&Xsh[1][xr * INP + xc * 4]);
#define STAGE_X(sp) cpasync16(((sp) & 1) ? xdst1 : xdst0, xsrc + (size_t)(sp) * INP)

    // wx for step sp from Xsh[sp&1] + wreg; valid on even lanes
#define WX_COMPUTE(sp, dst)                                                             \
    do {                                                                                \
        unsigned long long wacc[16];                                                    \
        _Pragma("unroll")                                                               \
        for (int o = 0; o < 16; o++) wacc[o] = 0ull;                                    \
        const float* xb = Xsh[(sp) & 1];                                                \
        _Pragma("unroll")                                                               \
        for (int qi = 0; qi < 2; qi++) {                                                \
            const int kb = qi * 128 + lane * 4;                                         \
            ulonglong2 xq[4];                                                           \
            _Pragma("unroll")                                                           \
            for (int b = 0; b < 4; b++)                                                 \
                xq[b] = *(const ulonglong2*)(xb + (wb * 4 + b) * INP + kb);             \
            _Pragma("unroll")                                                           \
            for (int b = 0; b < 4; b++)                                                 \
                _Pragma("unroll")                                                       \
                for (int j = 0; j < 4; j++) {                                           \
                    fma2(wacc[b * 4 + j], xq[b].x, wreg[qi][j].x);                      \
                    fma2(wacc[b * 4 + j], xq[b].y, wreg[qi][j].y);                      \
                }                                                                       \
        }                                                                               \
        float vv[16];                                                                   \
        _Pragma("unroll")                                                               \
        for (int o = 0; o < 16; o++) vv[o] = lo2(wacc[o]) + hi2(wacc[o]);               \
        BFLY16(vv, lane);                                                               \
        (dst) = vv[0] + wbj;                                                            \
    } while (0)

    // ---- prologue: stage X(0), X(1); compute wx(0) ----
    STAGE_X(0); CP_COMMIT();
    STAGE_X(1); CP_COMMIT();
    CP_WAIT1();                     // X(0) done (X(1) may be in flight)
    __syncthreads();
    float wx_cur;
    WX_COMPUTE(0, wx_cur);
    float h_last = 0.0f;

    for (int s = 0; s < SEQ; s++) {
        // 1. prefetch X(s+2); wait X(s+1); confirm h(s) flags (warp 0)
        if (s + 2 < SEQ) STAGE_X(s + 2);
        CP_COMMIT();
        CP_WAIT1();
        if (w == 0 && s > 0) {
            const unsigned tgt = base + (unsigned)s;
            unsigned v = tgt;
            if (lane < 16) v = ldacq(fgrp + lane);
            while (__any_sync(0xffffffffu, (int)(v - tgt) < 0)) {
                if (lane < 16 && (int)(v - tgt) < 0) v = ldacq(fgrp + lane);
            }
        }
        __syncthreads();   // bar1: X(s+1) visible; h(s) published; hsh reusable

        // 2. stage h(s) (issue LDGs first), wx(s+1) in the LDG shadow
        float4 hv0, hv1;
        if (s > 0) {
            const float* hsrc = g_hbuf + (s & 1) * (BATCH * HID) + (size_t)b0 * HID;
            hv0 = ((const float4*)hsrc)[t];
            hv1 = ((const float4*)hsrc)[t + THR];
        }
        float wx_next = 0.0f;
        if (s + 1 < SEQ) WX_COMPUTE(s + 1, wx_next);
        if (s > 0) {
            ((float4*)hsh)[t]       = hv0;
            ((float4*)hsh)[t + THR] = hv1;
        } else {
            ((float4*)hsh)[t]       = make_float4(0.f, 0.f, 0.f, 0.f);
            ((float4*)hsh)[t + THR] = make_float4(0.f, 0.f, 0.f, 0.f);
        }
        __syncthreads();   // bar2: hsh ready

        // 3. scan compute: 4b x 4j FFMA2 tile, U from registers
        unsigned long long acc[16];
#pragma unroll
        for (int o = 0; o < 16; o++) acc[o] = 0ull;
#pragma unroll
        for (int qi = 0; qi < 4; qi++) {
            const int kb = qi * 128 + lane * 4;
            ulonglong2 hq[4];
#pragma unroll
            for (int b = 0; b < 4; b++)
                hq[b] = *(const ulonglong2*)(hsh + (wb * 4 + b) * HID + kb);
#pragma unroll
            for (int b = 0; b < 4; b++)
#pragma unroll
                for (int j = 0; j < 4; j++) {
                    fma2(acc[b * 4 + j], hq[b].x, ureg[qi][j].x);
                    fma2(acc[b * 4 + j], hq[b].y, ureg[qi][j].y);
                }
        }
        float v[16];
#pragma unroll
        for (int o = 0; o < 16; o++) v[o] = lo2(acc[o]) + hi2(acc[o]);
        BFLY16(v, lane);

        if (writer) {
            float hnew = tanhf(wx_cur + ubj + v[0]);
            h_last = hnew;
            g_hbuf[((s + 1) & 1) * (BATCH * HID) + (size_t)babs * HID + jabs] = hnew;
        }

        // 4. order h stores before release
        __syncthreads();   // bar3
        if (t == 0) strel(g_flags + cta, base + (unsigned)s + 1u);

        wx_cur = wx_next;
    }

    // ---- fused readout ----
    if (writer) hsh[(wb * 4 + ob) * 32 + wj * 4 + ojl] = h_last;   // [8][32]
    __syncthreads();
    if (w == 0 && lane < 16) {
        const int b = lane >> 1, o = lane & 1;
        float p = 0.0f;
#pragma unroll
        for (int j = 0; j < 32; j++)
            p += hsh[b * 32 + j] * Vw[(size_t)(j0 + j) * 2 + o];
        g_opart[cta * 16 + lane] = p;
    }
    __syncthreads();
    if (t == 0) strel(g_flags + cta, base + (unsigned)SEQ + 1u);

    if (jg == 0) {
        if (w == 0) {
            const unsigned tgt = base + (unsigned)SEQ + 1u;
            unsigned v2 = tgt;
            if (lane < 16) v2 = ldacq(fgrp + lane);
            while (__any_sync(0xffffffffu, (int)(v2 - tgt) < 0)) {
                if (lane < 16 && (int)(v2 - tgt) < 0) v2 = ldacq(fgrp + lane);
            }
        }
        __syncthreads();
        if (w == 0 && lane < 16) {
            const int b = lane >> 1, o = lane & 1;
            float ssum = Vb[o];
#pragma unroll
            for (int g = 0; g < 16; g++)
                ssum += g_opart[(bg * 16 + g) * 16 + lane];
            out[(size_t)(b0 + b) * 2 + o] = 1.0f / (1.0f + expf(-ssum));
        }
    }
}

// =====================================================================
extern "C" void kernel_launch(void* const* d_in, const int* in_sizes, int n_in,
                              void* d_out, int out_size) {
    const float* x  = (const float*)d_in[0];
    const float* Ww = (const float*)d_in[1];
    const float* Wb = (const float*)d_in[2];
    const float* Uw = (const float*)d_in[3];
    const float* Ub = (const float*)d_in[4];
    const float* Vw = (const float*)d_in[5];
    const float* Vb = (const float*)d_in[6];
    float* out = (float*)d_out;

    fused_kernel<<<NCTA, THR>>>(x, Ww, Wb, Uw, Ub, Vw, Vb, out);
}